// round 15
// baseline (speedup 1.0000x reference)
#include <cuda_runtime.h>
#include <cuda_fp16.h>
#include <cstdint>
#include <math.h>

#define N_NODES 50000
#define N_EDGES 800000
#define FDIM    128
#define SCAN_B  ((N_NODES + 1023) / 1024)
#define AP      40
#define SMEM_BYTES (4 * 2 * 128 * AP * 2)
#define PERS_BLOCKS 592            // 148 SMs x 4 co-resident blocks (guaranteed)

// ---------------- static device scratch ----------------
__device__ int    g_deg[N_NODES];
__device__ int    g_cnt[N_NODES];
__device__ int    g_ofs[N_NODES];
__device__ int    g_rp[N_NODES + 1];
__device__ float  g_dinv[N_NODES];
__device__ int    g_col[N_EDGES];
__device__ float  g_wt[N_EDGES];
__device__ int    g_bsum[SCAN_B];
__device__ int    g_barc[16];
__device__ __half g_Xh [N_NODES * FDIM];
__device__ __half g_Xl [N_NODES * FDIM];
__device__ __half g_T1h[N_NODES * FDIM];
__device__ __half g_T1l[N_NODES * FDIM];
__device__ __half g_T2h[N_NODES * FDIM];
__device__ __half g_T2l[N_NODES * FDIM];
__device__ __half g_T3h[N_NODES * FDIM];
__device__ __half g_T3l[N_NODES * FDIM];
__device__ __half g_T4h[N_NODES * FDIM];
__device__ __half g_T4l[N_NODES * FDIM];
__device__ __half g_Hh [N_NODES * FDIM];
__device__ __half g_Hl [N_NODES * FDIM];
__device__ __half g_H2h[N_NODES * FDIM];
__device__ __half g_H2l[N_NODES * FDIM];
__device__ __half g_W0th[5 * 128 * 128];
__device__ __half g_W0tl[5 * 128 * 128];
__device__ __half g_W1th[5 * 128 * 128];
__device__ __half g_W1tl[5 * 128 * 128];
__device__ float  g_C2[5 * FDIM];
__device__ float  g_c0[1];

// ---------------- preprocessing ----------------
__global__ void k_zero() {
    int i = blockIdx.x * blockDim.x + threadIdx.x;
    if (i < N_NODES) { g_deg[i] = 0; g_cnt[i] = 0; }
    if (blockIdx.x == 0 && threadIdx.x < 16) g_barc[threadIdx.x] = 0;
}

__global__ void k_count(const int* __restrict__ ei) {
    int e = blockIdx.x * blockDim.x + threadIdx.x;
    if (e < N_EDGES) {
        int s = ei[e], d = ei[N_EDGES + e];
        if (s != d) {
            atomicAdd(&g_deg[s], 1);
            atomicAdd(&g_cnt[d], 1);
        }
    }
}

// scanA + dinv fused
__global__ void k_scanA() {
    __shared__ int wsum[32];
    int tid  = threadIdx.x;
    int lane = tid & 31, wid = tid >> 5;
    int i = blockIdx.x * 1024 + tid;

    if (i < N_NODES) {
        int dg = g_deg[i];
        g_dinv[i] = (dg > 0) ? rsqrtf((float)dg) : 0.0f;
    }

    int v = (i < N_NODES) ? g_cnt[i] : 0;
    int x = v;
    #pragma unroll
    for (int off = 1; off < 32; off <<= 1) {
        int y = __shfl_up_sync(0xFFFFFFFFu, x, off);
        if (lane >= off) x += y;
    }
    if (lane == 31) wsum[wid] = x;
    __syncthreads();
    if (wid == 0) {
        int y = wsum[lane];
        #pragma unroll
        for (int off = 1; off < 32; off <<= 1) {
            int z = __shfl_up_sync(0xFFFFFFFFu, y, off);
            if (lane >= off) y += z;
        }
        wsum[lane] = y;
    }
    __syncthreads();
    int excl = x - v + (wid > 0 ? wsum[wid - 1] : 0);
    if (i < N_NODES) g_rp[i] = excl;
    if (tid == 0) g_bsum[blockIdx.x] = wsum[31];
}

// scanC with inlined block-sum prefix (64-lane shuffle scan of g_bsum)
__global__ void k_scanC() {
    __shared__ int ws[2];
    __shared__ int bofs_s;
    int tid  = threadIdx.x;
    int lane = tid & 31, w5 = tid >> 5;

    int v = (tid < SCAN_B) ? g_bsum[tid] : 0;
    int x = v;
    #pragma unroll
    for (int off = 1; off < 32; off <<= 1) {
        int y = __shfl_up_sync(0xFFFFFFFFu, x, off);
        if (lane >= off) x += y;
    }
    if (tid < 64 && lane == 31) ws[w5] = x;
    __syncthreads();
    int excl = 0;
    if (tid < 64) excl = x - v + ((w5 == 1) ? ws[0] : 0);
    if (tid == blockIdx.x) bofs_s = excl;     // blockIdx.x < SCAN_B <= 49 < 64
    if (blockIdx.x == SCAN_B - 1 && tid == SCAN_B - 1)
        g_rp[N_NODES] = excl + v;
    __syncthreads();

    int i = blockIdx.x * 1024 + tid;
    if (i < N_NODES) {
        int r = g_rp[i] + bofs_s;
        g_rp[i]  = r;
        g_ofs[i] = r;
    }
}

__global__ void k_fill(const int* __restrict__ ei) {
    int e = blockIdx.x * blockDim.x + threadIdx.x;
    if (e < N_EDGES) {
        int s = ei[e], d = ei[N_EDGES + e];
        if (s != d) {
            int p = atomicAdd(&g_ofs[d], 1);
            g_col[p] = s;
            g_wt[p]  = -g_dinv[s] * g_dinv[d];
        }
    }
}

// ---------------- fused init: fold + wsplit(W0) + wsplit(W1) + h16 -------
#define INIT_FOLD   5
#define INIT_WSP    320
#define INIT_H16    ((N_NODES * 32 + 255) / 256)
#define INIT_BLOCKS (INIT_FOLD + 2 * INIT_WSP + INIT_H16)

__device__ __forceinline__ void wsplit_body(const float* __restrict__ W,
                                            __half* __restrict__ Wh,
                                            __half* __restrict__ Wl, int o) {
    int s = o >> 14, r = o & 16383, n = r >> 7, k = r & 127;
    float w = W[s * 16384 + k * 128 + n];
    __half h = __float2half_rn(w);
    Wh[o] = h;
    Wl[o] = __float2half_rn(w - __half2float(h));
}

__global__ void k_init(const float* __restrict__ W0, const float* __restrict__ W1,
                       const float* __restrict__ W2, const float* __restrict__ b2,
                       const float* __restrict__ Wl, const float* __restrict__ bl,
                       const float* __restrict__ x,
                       __half* __restrict__ W0h, __half* __restrict__ W0l,
                       __half* __restrict__ W1h, __half* __restrict__ W1l,
                       __half* __restrict__ Xh,  __half* __restrict__ Xl) {
    const int b = blockIdx.x;
    if (b < INIT_FOLD) {
        int k = b, f = threadIdx.x;
        if (f < 128) {
            const float* row = W2 + ((size_t)k * 128 + f) * 128;
            float s = 0.f;
            #pragma unroll 4
            for (int w = 0; w < 128; ++w) s += row[w] * Wl[w];
            g_C2[k * 128 + f] = s;
            if (k == 0 && f == 0) {
                float c = bl[0];
                for (int w = 0; w < 128; ++w) c += b2[w] * Wl[w];
                g_c0[0] = c;
            }
        }
    } else if (b < INIT_FOLD + INIT_WSP) {
        int o = (b - INIT_FOLD) * 256 + threadIdx.x;
        if (o < 5 * 128 * 128) wsplit_body(W0, W0h, W0l, o);
    } else if (b < INIT_FOLD + 2 * INIT_WSP) {
        int o = (b - INIT_FOLD - INIT_WSP) * 256 + threadIdx.x;
        if (o < 5 * 128 * 128) wsplit_body(W1, W1h, W1l, o);
    } else {
        int i = (b - INIT_FOLD - 2 * INIT_WSP) * 256 + threadIdx.x;
        if (i < N_NODES * 32) {
            float4 v = ((const float4*)x)[i];
            __half2 a = __floats2half2_rn(v.x, v.y);
            __half2 bb = __floats2half2_rn(v.z, v.w);
            float2 fa = __half22float2(a), fb = __half22float2(bb);
            __half2 la = __floats2half2_rn(v.x - fa.x, v.y - fa.y);
            __half2 lb = __floats2half2_rn(v.z - fb.x, v.w - fb.y);
            uint2 u, ul;
            u.x  = *reinterpret_cast<uint32_t*>(&a);
            u.y  = *reinterpret_cast<uint32_t*>(&bb);
            ul.x = *reinterpret_cast<uint32_t*>(&la);
            ul.y = *reinterpret_cast<uint32_t*>(&lb);
            ((uint2*)Xh)[i] = u;
            ((uint2*)Xl)[i] = ul;
        }
    }
}

// ---------------- helpers ----------------
__device__ __forceinline__ float4 load_hl(const __half* __restrict__ h,
                                          const __half* __restrict__ l,
                                          int idx) {
    uint2 uh = ((const uint2*)h)[idx];
    uint2 ul = ((const uint2*)l)[idx];
    float2 h0 = __half22float2(*reinterpret_cast<__half2*>(&uh.x));
    float2 h1 = __half22float2(*reinterpret_cast<__half2*>(&uh.y));
    float2 l0 = __half22float2(*reinterpret_cast<__half2*>(&ul.x));
    float2 l1 = __half22float2(*reinterpret_cast<__half2*>(&ul.y));
    float4 r;
    r.x = h0.x + l0.x; r.y = h0.y + l0.y;
    r.z = h1.x + l1.x; r.w = h1.y + l1.y;
    return r;
}
__device__ __forceinline__ void store_hl(__half* __restrict__ h,
                                         __half* __restrict__ l,
                                         int idx, float4 r) {
    __half2 h0 = __floats2half2_rn(r.x, r.y);
    __half2 h1 = __floats2half2_rn(r.z, r.w);
    float2 f0 = __half22float2(h0), f1 = __half22float2(h1);
    __half2 l0 = __floats2half2_rn(r.x - f0.x, r.y - f0.y);
    __half2 l1 = __floats2half2_rn(r.z - f1.x, r.w - f1.y);
    uint2 hu, lu;
    hu.x = *reinterpret_cast<uint32_t*>(&h0);
    hu.y = *reinterpret_cast<uint32_t*>(&h1);
    lu.x = *reinterpret_cast<uint32_t*>(&l0);
    lu.y = *reinterpret_cast<uint32_t*>(&l1);
    ((uint2*)h)[idx] = hu;
    ((uint2*)l)[idx] = lu;
}

__device__ __forceinline__ void gacc(float& ax, float& ay, float& az, float& aw,
                                     uint2 u, float w) {
    float2 a = __half22float2(*reinterpret_cast<__half2*>(&u.x));
    float2 b = __half22float2(*reinterpret_cast<__half2*>(&u.y));
    ax += w * a.x; ay += w * a.y; az += w * b.x; aw += w * b.y;
}

__device__ __forceinline__ void gather_row(
    const __half* __restrict__ vinH, int beg, int end, int lane,
    float& ax, float& ay, float& az, float& aw)
{
    int j = beg;
    for (; j + 7 < end; j += 8) {
        int   s[8];
        float w[8];
        uint2 u[8];
        #pragma unroll
        for (int q = 0; q < 8; ++q) { s[q] = g_col[j + q]; w[q] = g_wt[j + q]; }
        #pragma unroll
        for (int q = 0; q < 8; ++q)
            u[q] = ((const uint2*)(vinH + (size_t)s[q] * 128))[lane];
        #pragma unroll
        for (int q = 0; q < 8; ++q) gacc(ax, ay, az, aw, u[q], w[q]);
    }
    for (; j + 1 < end; j += 2) {
        int   s0 = g_col[j],  s1 = g_col[j + 1];
        float w0 = g_wt[j],   w1 = g_wt[j + 1];
        uint2 u0 = ((const uint2*)(vinH + (size_t)s0 * 128))[lane];
        uint2 u1 = ((const uint2*)(vinH + (size_t)s1 * 128))[lane];
        gacc(ax, ay, az, aw, u0, w0);
        gacc(ax, ay, az, aw, u1, w1);
    }
    if (j < end) {
        int   s0 = g_col[j];
        float w0 = g_wt[j];
        uint2 u0 = ((const uint2*)(vinH + (size_t)s0 * 128))[lane];
        gacc(ax, ay, az, aw, u0, w0);
    }
}

// ---------------- global barrier (slot-per-barrier, counter only) --------
__device__ __forceinline__ void gbar(int slot) {
    __syncthreads();
    if (threadIdx.x == 0) {
        __threadfence();
        atomicAdd(&g_barc[slot], 1);
        while (atomicAdd(&g_barc[slot], 0) < PERS_BLOCKS) __nanosleep(64);
        __threadfence();
    }
    __syncthreads();
}

// ---------------- persistent per-layer SpMV chain ----------------
struct Phase {
    const __half* vin;
    const __half* pvh;
    const __half* pvl;
    __half* oh;
    __half* ol;
    int cheb;
};
struct Chain {
    Phase ph[4];
    int nph;      // number of plain spmv phases (4 or 3)
    int barBase;  // first barrier slot
    int doOut;    // run fused head phase after the spmv phases
    const __half *O3h, *O3l, *O2h, *O2l, *OHh, *OHl, *O1h, *O1l;
    float* out;
};

__global__ __launch_bounds__(256, 4) void k_layer(Chain c) {
    __shared__ float c2[5 * 128];
    if (c.doOut) {
        for (int i = threadIdx.x; i < 5 * 128; i += 256) c2[i] = g_C2[i];
    }
    const int wloc = threadIdx.x >> 5;
    const int lane = threadIdx.x & 31;

    for (int p = 0; p < c.nph; ++p) {
        if (p > 0) gbar(c.barBase + p - 1);
        const Phase F = c.ph[p];
        for (int w = blockIdx.x * 8 + wloc; w < N_NODES; w += PERS_BLOCKS * 8) {
            float4 pv = make_float4(0.f, 0.f, 0.f, 0.f);
            if (F.cheb) pv = load_hl(F.pvh, F.pvl, w * 32 + lane);
            float ax = 0.f, ay = 0.f, az = 0.f, aw = 0.f;
            gather_row(F.vin, g_rp[w], g_rp[w + 1], lane, ax, ay, az, aw);
            float4 r;
            if (F.cheb) {
                r.x = 2.0f * ax - pv.x;
                r.y = 2.0f * ay - pv.y;
                r.z = 2.0f * az - pv.z;
                r.w = 2.0f * aw - pv.w;
            } else {
                r.x = ax; r.y = ay; r.z = az; r.w = aw;
            }
            store_hl(F.oh, F.ol, w * 32 + lane, r);
        }
    }

    if (c.doOut) {
        gbar(c.barBase + c.nph - 1);
        for (int w = blockIdx.x * 8 + wloc; w < N_NODES; w += PERS_BLOCKS * 8) {
            const int idx = w * 32 + lane;
            float4 p = load_hl(c.O2h, c.O2l, idx);
            float ax = 0.f, ay = 0.f, az = 0.f, aw = 0.f;
            gather_row(c.O3h, g_rp[w], g_rp[w + 1], lane, ax, ay, az, aw);
            float4 t4;
            t4.x = 2.0f * ax - p.x;
            t4.y = 2.0f * ay - p.y;
            t4.z = 2.0f * az - p.z;
            t4.w = 2.0f * aw - p.w;

            const int cc = lane * 4;
            float s;
            {
                const float* w4 = c2 + 4 * 128 + cc;
                s = t4.x * w4[0] + t4.y * w4[1] + t4.z * w4[2] + t4.w * w4[3];
            }
            {
                float4 h = load_hl(c.OHh, c.OHl, idx);
                const float* w0 = c2 + 0 * 128 + cc;
                s += h.x * w0[0] + h.y * w0[1] + h.z * w0[2] + h.w * w0[3];
            }
            {
                float4 h = load_hl(c.O1h, c.O1l, idx);
                const float* w1 = c2 + 1 * 128 + cc;
                s += h.x * w1[0] + h.y * w1[1] + h.z * w1[2] + h.w * w1[3];
            }
            {
                const float* w2 = c2 + 2 * 128 + cc;
                s += p.x * w2[0] + p.y * w2[1] + p.z * w2[2] + p.w * w2[3];
            }
            {
                float4 h = load_hl(c.O3h, c.O3l, idx);
                const float* w3 = c2 + 3 * 128 + cc;
                s += h.x * w3[0] + h.y * w3[1] + h.z * w3[2] + h.w * w3[3];
            }
            #pragma unroll
            for (int off = 16; off > 0; off >>= 1)
                s += __shfl_xor_sync(0xFFFFFFFFu, s, off);
            if (lane == 0) c.out[w] = s + g_c0[0];
        }
    }
}

// ---------------- tensor-core GEMM: cp.async double-buffered ----------
struct P5 { const __half* h[5]; const __half* l[5]; };

__device__ __forceinline__ void mma16816(float* d, const uint32_t* a, const uint32_t* b) {
    asm volatile(
        "mma.sync.aligned.m16n8k16.row.col.f32.f16.f16.f32 "
        "{%0,%1,%2,%3}, {%4,%5,%6,%7}, {%8,%9}, {%0,%1,%2,%3};"
        : "+f"(d[0]), "+f"(d[1]), "+f"(d[2]), "+f"(d[3])
        : "r"(a[0]), "r"(a[1]), "r"(a[2]), "r"(a[3]), "r"(b[0]), "r"(b[1]));
}

__device__ __forceinline__ void cpa16(uint32_t dst, const void* src, int srcsize) {
    asm volatile("cp.async.cg.shared.global [%0], [%1], 16, %2;"
                 :: "r"(dst), "l"(src), "r"(srcsize));
}

template <bool RELU>
__global__ __launch_bounds__(256, 2)
void k_gemm_mma(P5 A, const __half* __restrict__ Bh, const __half* __restrict__ Bl,
                const float* __restrict__ bias,
                __half* __restrict__ Ch, __half* __restrict__ Cl) {
    extern __shared__ __align__(16) __half sm[];
    const int ARR = 128 * AP;

    const int tid  = threadIdx.x;
    const int wid  = tid >> 5, lane = tid & 31;
    const int g    = lane >> 2, t = lane & 3;
    const int wm   = wid & 3;
    const int wn   = wid >> 2;
    const int m0   = blockIdx.x * 128;

    uint32_t smBase;
    asm("{ .reg .u64 tt; cvta.to.shared.u64 tt, %1; cvt.u32.u64 %0, tt; }"
        : "=r"(smBase) : "l"(sm));

    float acc[2][8][4];
    #pragma unroll
    for (int mt = 0; mt < 2; ++mt)
        #pragma unroll
        for (int nt = 0; nt < 8; ++nt)
            #pragma unroll
            for (int q = 0; q < 4; ++q) acc[mt][nt][q] = 0.f;

    auto do_stage = [&](int c, int buf) {
        const int s = c >> 2, k0 = (c & 3) * 32;
        const __half* Ah = A.h[s];
        const __half* Al = A.l[s];
        const size_t bofs = (size_t)s * 16384 + k0;
        const uint32_t base = smBase + (uint32_t)(buf * 4 * ARR) * 2;
        #pragma unroll
        for (int i = 0; i < 2; ++i) {
            int q = tid + i * 256;
            int row = q >> 2, seg = q & 3;
            int gm = m0 + row;
            int ok  = (gm < N_NODES) ? 16 : 0;
            int gmc = (gm < N_NODES) ? gm : 0;
            uint32_t so = (uint32_t)((row * AP + seg * 8) * 2);
            cpa16(base + 0 * ARR * 2 + so, Ah + (size_t)gmc * 128 + k0 + seg * 8, ok);
            cpa16(base + 1 * ARR * 2 + so, Al + (size_t)gmc * 128 + k0 + seg * 8, ok);
            cpa16(base + 2 * ARR * 2 + so, Bh + bofs + (size_t)row * 128 + seg * 8, 16);
            cpa16(base + 3 * ARR * 2 + so, Bl + bofs + (size_t)row * 128 + seg * 8, 16);
        }
    };

    do_stage(0, 0);
    asm volatile("cp.async.commit_group;" ::: "memory");

    #pragma unroll 1
    for (int c = 0; c < 20; ++c) {
        const int cur = c & 1;
        if (c + 1 < 20) {
            do_stage(c + 1, cur ^ 1);
            asm volatile("cp.async.commit_group;" ::: "memory");
            asm volatile("cp.async.wait_group 1;" ::: "memory");
        } else {
            asm volatile("cp.async.wait_group 0;" ::: "memory");
        }
        __syncthreads();

        const __half* pAh = sm + (cur * 4 + 0) * ARR;
        const __half* pAl = sm + (cur * 4 + 1) * ARR;
        const __half* pBh = sm + (cur * 4 + 2) * ARR;
        const __half* pBl = sm + (cur * 4 + 3) * ARR;

        #pragma unroll
        for (int ks = 0; ks < 2; ++ks) {
            const int kb = ks * 16 + 2 * t;
            uint32_t bf[8][2], ah[2][4], al[2][4];
            #pragma unroll
            for (int nt = 0; nt < 8; ++nt) {
                const int nb = (wn * 64 + nt * 8 + g) * AP + kb;
                bf[nt][0] = *(const uint32_t*)&pBh[nb];
                bf[nt][1] = *(const uint32_t*)&pBh[nb + 8];
            }
            #pragma unroll
            for (int mt = 0; mt < 2; ++mt) {
                const int rb = (wm * 32 + mt * 16 + g) * AP + kb;
                ah[mt][0] = *(const uint32_t*)&pAh[rb];
                ah[mt][1] = *(const uint32_t*)&pAh[rb + 8 * AP];
                ah[mt][2] = *(const uint32_t*)&pAh[rb + 8];
                ah[mt][3] = *(const uint32_t*)&pAh[rb + 8 * AP + 8];
                al[mt][0] = *(const uint32_t*)&pAl[rb];
                al[mt][1] = *(const uint32_t*)&pAl[rb + 8 * AP];
                al[mt][2] = *(const uint32_t*)&pAl[rb + 8];
                al[mt][3] = *(const uint32_t*)&pAl[rb + 8 * AP + 8];
            }
            #pragma unroll
            for (int mt = 0; mt < 2; ++mt)
                #pragma unroll
                for (int nt = 0; nt < 8; ++nt) mma16816(acc[mt][nt], ah[mt], bf[nt]);
            #pragma unroll
            for (int mt = 0; mt < 2; ++mt)
                #pragma unroll
                for (int nt = 0; nt < 8; ++nt) mma16816(acc[mt][nt], al[mt], bf[nt]);
            #pragma unroll
            for (int nt = 0; nt < 8; ++nt) {
                const int nb = (wn * 64 + nt * 8 + g) * AP + kb;
                bf[nt][0] = *(const uint32_t*)&pBl[nb];
                bf[nt][1] = *(const uint32_t*)&pBl[nb + 8];
            }
            #pragma unroll
            for (int mt = 0; mt < 2; ++mt)
                #pragma unroll
                for (int nt = 0; nt < 8; ++nt) mma16816(acc[mt][nt], ah[mt], bf[nt]);
        }
        __syncthreads();
    }

    #pragma unroll
    for (int mt = 0; mt < 2; ++mt) {
        #pragma unroll
        for (int half = 0; half < 2; ++half) {
            const int row = m0 + wm * 32 + mt * 16 + g + half * 8;
            if (row < N_NODES) {
                #pragma unroll
                for (int nt = 0; nt < 8; ++nt) {
                    const int col = wn * 64 + nt * 8 + 2 * t;
                    float v0 = acc[mt][nt][half * 2 + 0] + __ldg(bias + col);
                    float v1 = acc[mt][nt][half * 2 + 1] + __ldg(bias + col + 1);
                    if (RELU) { v0 = fmaxf(v0, 0.f); v1 = fmaxf(v1, 0.f); }
                    __half2 h2 = __floats2half2_rn(v0, v1);
                    float2 hf = __half22float2(h2);
                    __half2 l2 = __floats2half2_rn(v0 - hf.x, v1 - hf.y);
                    *(uint32_t*)(Ch + (size_t)row * 128 + col) =
                        *reinterpret_cast<uint32_t*>(&h2);
                    *(uint32_t*)(Cl + (size_t)row * 128 + col) =
                        *reinterpret_cast<uint32_t*>(&l2);
                }
            }
        }
    }
}

// ---------------- launch --------------------------------------------------
extern "C" void kernel_launch(void* const* d_in, const int* in_sizes, int n_in,
                              void* d_out, int out_size) {
    const float* x  = (const float*)d_in[0];
    const int*   ei = (const int*)  d_in[1];
    const float* W0 = (const float*)d_in[2];
    const float* b0 = (const float*)d_in[3];
    const float* W1 = (const float*)d_in[4];
    const float* b1 = (const float*)d_in[5];
    const float* W2 = (const float*)d_in[6];
    const float* b2 = (const float*)d_in[7];
    const float* Wl = (const float*)d_in[8];
    const float* bl = (const float*)d_in[9];
    float* out = (float*)d_out;

    __half *Xh, *Xl, *T1h, *T1l, *T2h, *T2l, *T3h, *T3l, *T4h, *T4l;
    __half *Hh, *Hl, *H2h, *H2l;
    __half *W0th, *W0tl, *W1th, *W1tl;
    cudaGetSymbolAddress((void**)&Xh,   g_Xh);
    cudaGetSymbolAddress((void**)&Xl,   g_Xl);
    cudaGetSymbolAddress((void**)&T1h,  g_T1h);
    cudaGetSymbolAddress((void**)&T1l,  g_T1l);
    cudaGetSymbolAddress((void**)&T2h,  g_T2h);
    cudaGetSymbolAddress((void**)&T2l,  g_T2l);
    cudaGetSymbolAddress((void**)&T3h,  g_T3h);
    cudaGetSymbolAddress((void**)&T3l,  g_T3l);
    cudaGetSymbolAddress((void**)&T4h,  g_T4h);
    cudaGetSymbolAddress((void**)&T4l,  g_T4l);
    cudaGetSymbolAddress((void**)&Hh,   g_Hh);
    cudaGetSymbolAddress((void**)&Hl,   g_Hl);
    cudaGetSymbolAddress((void**)&H2h,  g_H2h);
    cudaGetSymbolAddress((void**)&H2l,  g_H2l);
    cudaGetSymbolAddress((void**)&W0th, g_W0th);
    cudaGetSymbolAddress((void**)&W0tl, g_W0tl);
    cudaGetSymbolAddress((void**)&W1th, g_W1th);
    cudaGetSymbolAddress((void**)&W1tl, g_W1tl);

    cudaFuncSetAttribute(k_gemm_mma<true>,
                         cudaFuncAttributeMaxDynamicSharedMemorySize, SMEM_BYTES);

    const int nb_n = (N_NODES + 255) / 256;
    const int nb_e = (N_EDGES + 255) / 256;
    const int gemm_blocks = (N_NODES + 127) / 128;

    k_zero <<<nb_n, 256>>>();
    k_count<<<nb_e, 256>>>(ei);
    k_scanA<<<SCAN_B, 1024>>>();
    k_scanC<<<SCAN_B, 1024>>>();
    k_fill <<<nb_e, 256>>>(ei);
    k_init <<<INIT_BLOCKS, 256>>>(W0, W1, W2, b2, Wl, bl, x,
                                  W0th, W0tl, W1th, W1tl, Xh, Xl);

    // ---- layer 0: persistent 4-matvec chain ----
    {
        Chain c = {};
        c.ph[0] = { Xh,  nullptr, nullptr, T1h, T1l, 0 };
        c.ph[1] = { T1h, Xh,  Xl,  T2h, T2l, 1 };
        c.ph[2] = { T2h, T1h, T1l, T3h, T3l, 1 };
        c.ph[3] = { T3h, T2h, T2l, T4h, T4l, 1 };
        c.nph = 4; c.barBase = 0; c.doOut = 0;
        k_layer<<<PERS_BLOCKS, 256>>>(c);
    }
    { P5 a;
      a.h[0]=Xh;  a.h[1]=T1h; a.h[2]=T2h; a.h[3]=T3h; a.h[4]=T4h;
      a.l[0]=Xl;  a.l[1]=T1l; a.l[2]=T2l; a.l[3]=T3l; a.l[4]=T4l;
      k_gemm_mma<true><<<gemm_blocks, 256, SMEM_BYTES>>>(
          a, W0th, W0tl, b0, Hh, Hl); }

    // ---- layer 1 ----
    {
        Chain c = {};
        c.ph[0] = { Hh,  nullptr, nullptr, T1h, T1l, 0 };
        c.ph[1] = { T1h, Hh,  Hl,  T2h, T2l, 1 };
        c.ph[2] = { T2h, T1h, T1l, T3h, T3l, 1 };
        c.ph[3] = { T3h, T2h, T2l, T4h, T4l, 1 };
        c.nph = 4; c.barBase = 3; c.doOut = 0;
        k_layer<<<PERS_BLOCKS, 256>>>(c);
    }
    { P5 a;
      a.h[0]=Hh;  a.h[1]=T1h; a.h[2]=T2h; a.h[3]=T3h; a.h[4]=T4h;
      a.l[0]=Hl;  a.l[1]=T1l; a.l[2]=T2l; a.l[3]=T3l; a.l[4]=T4l;
      k_gemm_mma<true><<<gemm_blocks, 256, SMEM_BYTES>>>(
          a, W1th, W1tl, b1, H2h, H2l); }

    // ---- layer 2: 3 matvecs + fused head, one persistent launch ----
    {
        Chain c = {};
        c.ph[0] = { H2h, nullptr, nullptr, T1h, T1l, 0 };
        c.ph[1] = { T1h, H2h, H2l, T2h, T2l, 1 };
        c.ph[2] = { T2h, T1h, T1l, T3h, T3l, 1 };
        c.nph = 3; c.barBase = 6; c.doOut = 1;
        c.O3h = T3h; c.O3l = T3l;
        c.O2h = T2h; c.O2l = T2l;
        c.OHh = H2h; c.OHl = H2l;
        c.O1h = T1h; c.O1l = T1l;
        c.out = out;
        k_layer<<<PERS_BLOCKS, 256>>>(c);
    }
}

// round 17
// speedup vs baseline: 1.0966x; 1.0966x over previous
#include <cuda_runtime.h>
#include <cuda_fp16.h>
#include <cstdint>
#include <math.h>

#define N_NODES 50000
#define N_EDGES 800000
#define FDIM    128
#define SCAN_B  ((N_NODES + 1023) / 1024)
#define AP      40                  // padded halves per smem row (80B)
#define SMEM_BYTES (4 * 2 * 128 * AP * 2)

// ---------------- static device scratch ----------------
__device__ int    g_deg[N_NODES];
__device__ int    g_cnt[N_NODES];
__device__ int    g_ofs[N_NODES];
__device__ int    g_rp[N_NODES + 1];
__device__ float  g_dinv[N_NODES];
__device__ int    g_col[N_EDGES];
__device__ float  g_wt[N_EDGES];
__device__ int    g_bsum[SCAN_B];
__device__ __half g_Xh [N_NODES * FDIM];
__device__ __half g_Xl [N_NODES * FDIM];
__device__ __half g_T1h[N_NODES * FDIM];
__device__ __half g_T1l[N_NODES * FDIM];
__device__ __half g_T2h[N_NODES * FDIM];
__device__ __half g_T2l[N_NODES * FDIM];
__device__ __half g_T3h[N_NODES * FDIM];
__device__ __half g_T3l[N_NODES * FDIM];
__device__ __half g_T4h[N_NODES * FDIM];
__device__ __half g_T4l[N_NODES * FDIM];
__device__ __half g_Hh [N_NODES * FDIM];
__device__ __half g_Hl [N_NODES * FDIM];
__device__ __half g_H2h[N_NODES * FDIM];
__device__ __half g_H2l[N_NODES * FDIM];
__device__ __half g_W0th[5 * 128 * 128];
__device__ __half g_W0tl[5 * 128 * 128];
__device__ __half g_W1th[5 * 128 * 128];
__device__ __half g_W1tl[5 * 128 * 128];
__device__ float  g_C2[5 * FDIM];
__device__ float  g_c0[1];

// ---------------- preprocessing ----------------
__global__ void k_zero() {
    int i = blockIdx.x * blockDim.x + threadIdx.x;
    if (i < N_NODES) { g_deg[i] = 0; g_cnt[i] = 0; }
}

// ---------------- fused count + init (independent work, one launch) ------
#define NB_E        ((N_EDGES + 255) / 256)
#define INIT_FOLD   5
#define INIT_WSP    320
#define INIT_H16    ((N_NODES * 32 + 255) / 256)
#define CI_BLOCKS   (NB_E + INIT_FOLD + 2 * INIT_WSP + INIT_H16)

__device__ __forceinline__ void wsplit_body(const float* __restrict__ W,
                                            __half* __restrict__ Wh,
                                            __half* __restrict__ Wl, int o) {
    int s = o >> 14, r = o & 16383, n = r >> 7, k = r & 127;
    float w = W[s * 16384 + k * 128 + n];
    __half h = __float2half_rn(w);
    Wh[o] = h;
    Wl[o] = __float2half_rn(w - __half2float(h));
}

__global__ void k_count_init(const int* __restrict__ ei,
                             const float* __restrict__ W0, const float* __restrict__ W1,
                             const float* __restrict__ W2, const float* __restrict__ b2,
                             const float* __restrict__ Wl, const float* __restrict__ bl,
                             const float* __restrict__ x,
                             __half* __restrict__ W0h, __half* __restrict__ W0l,
                             __half* __restrict__ W1h, __half* __restrict__ W1l,
                             __half* __restrict__ Xh,  __half* __restrict__ Xl) {
    const int b = blockIdx.x;
    if (b < NB_E) {
        int e = b * 256 + threadIdx.x;
        if (e < N_EDGES) {
            int s = ei[e], d = ei[N_EDGES + e];
            if (s != d) {
                atomicAdd(&g_deg[s], 1);
                atomicAdd(&g_cnt[d], 1);
            }
        }
    } else if (b < NB_E + INIT_FOLD) {
        int k = b - NB_E, f = threadIdx.x;
        if (f < 128) {
            const float* row = W2 + ((size_t)k * 128 + f) * 128;
            float s = 0.f;
            #pragma unroll 4
            for (int w = 0; w < 128; ++w) s += row[w] * Wl[w];
            g_C2[k * 128 + f] = s;
            if (k == 0 && f == 0) {
                float c = bl[0];
                for (int w = 0; w < 128; ++w) c += b2[w] * Wl[w];
                g_c0[0] = c;
            }
        }
    } else if (b < NB_E + INIT_FOLD + INIT_WSP) {
        int o = (b - NB_E - INIT_FOLD) * 256 + threadIdx.x;
        if (o < 5 * 128 * 128) wsplit_body(W0, W0h, W0l, o);
    } else if (b < NB_E + INIT_FOLD + 2 * INIT_WSP) {
        int o = (b - NB_E - INIT_FOLD - INIT_WSP) * 256 + threadIdx.x;
        if (o < 5 * 128 * 128) wsplit_body(W1, W1h, W1l, o);
    } else {
        int i = (b - NB_E - INIT_FOLD - 2 * INIT_WSP) * 256 + threadIdx.x;
        if (i < N_NODES * 32) {
            float4 v = ((const float4*)x)[i];
            __half2 a = __floats2half2_rn(v.x, v.y);
            __half2 bb = __floats2half2_rn(v.z, v.w);
            float2 fa = __half22float2(a), fb = __half22float2(bb);
            __half2 la = __floats2half2_rn(v.x - fa.x, v.y - fa.y);
            __half2 lb = __floats2half2_rn(v.z - fb.x, v.w - fb.y);
            uint2 u, ul;
            u.x  = *reinterpret_cast<uint32_t*>(&a);
            u.y  = *reinterpret_cast<uint32_t*>(&bb);
            ul.x = *reinterpret_cast<uint32_t*>(&la);
            ul.y = *reinterpret_cast<uint32_t*>(&lb);
            ((uint2*)Xh)[i] = u;
            ((uint2*)Xl)[i] = ul;
        }
    }
}

// scanA + dinv fused
__global__ void k_scanA() {
    __shared__ int wsum[32];
    int tid  = threadIdx.x;
    int lane = tid & 31, wid = tid >> 5;
    int i = blockIdx.x * 1024 + tid;

    if (i < N_NODES) {
        int dg = g_deg[i];
        g_dinv[i] = (dg > 0) ? rsqrtf((float)dg) : 0.0f;
    }

    int v = (i < N_NODES) ? g_cnt[i] : 0;
    int x = v;
    #pragma unroll
    for (int off = 1; off < 32; off <<= 1) {
        int y = __shfl_up_sync(0xFFFFFFFFu, x, off);
        if (lane >= off) x += y;
    }
    if (lane == 31) wsum[wid] = x;
    __syncthreads();
    if (wid == 0) {
        int y = wsum[lane];
        #pragma unroll
        for (int off = 1; off < 32; off <<= 1) {
            int z = __shfl_up_sync(0xFFFFFFFFu, y, off);
            if (lane >= off) y += z;
        }
        wsum[lane] = y;
    }
    __syncthreads();
    int excl = x - v + (wid > 0 ? wsum[wid - 1] : 0);
    if (i < N_NODES) g_rp[i] = excl;
    if (tid == 0) g_bsum[blockIdx.x] = wsum[31];
}

// scanC with inlined block-sum prefix (64-lane shuffle scan of g_bsum)
__global__ void k_scanC() {
    __shared__ int ws[2];
    __shared__ int bofs_s;
    int tid  = threadIdx.x;
    int lane = tid & 31, w5 = tid >> 5;

    int v = (tid < SCAN_B) ? g_bsum[tid] : 0;
    int x = v;
    #pragma unroll
    for (int off = 1; off < 32; off <<= 1) {
        int y = __shfl_up_sync(0xFFFFFFFFu, x, off);
        if (lane >= off) x += y;
    }
    if (tid < 64 && lane == 31) ws[w5] = x;
    __syncthreads();
    int excl = 0;
    if (tid < 64) excl = x - v + ((w5 == 1) ? ws[0] : 0);
    if (tid == blockIdx.x) bofs_s = excl;     // blockIdx.x < SCAN_B <= 49 < 64
    if (blockIdx.x == SCAN_B - 1 && tid == SCAN_B - 1)
        g_rp[N_NODES] = excl + v;
    __syncthreads();

    int i = blockIdx.x * 1024 + tid;
    if (i < N_NODES) {
        int r = g_rp[i] + bofs_s;
        g_rp[i]  = r;
        g_ofs[i] = r;
    }
}

__global__ void k_fill(const int* __restrict__ ei) {
    int e = blockIdx.x * blockDim.x + threadIdx.x;
    if (e < N_EDGES) {
        int s = ei[e], d = ei[N_EDGES + e];
        if (s != d) {
            int p = atomicAdd(&g_ofs[d], 1);
            g_col[p] = s;
            g_wt[p]  = -g_dinv[s] * g_dinv[d];
        }
    }
}

// ---------------- helpers: hi/lo fp16 pair <-> fp32x4 ----------------
__device__ __forceinline__ float4 load_hl(const __half* __restrict__ h,
                                          const __half* __restrict__ l,
                                          int idx) {
    uint2 uh = ((const uint2*)h)[idx];
    uint2 ul = ((const uint2*)l)[idx];
    float2 h0 = __half22float2(*reinterpret_cast<__half2*>(&uh.x));
    float2 h1 = __half22float2(*reinterpret_cast<__half2*>(&uh.y));
    float2 l0 = __half22float2(*reinterpret_cast<__half2*>(&ul.x));
    float2 l1 = __half22float2(*reinterpret_cast<__half2*>(&ul.y));
    float4 r;
    r.x = h0.x + l0.x; r.y = h0.y + l0.y;
    r.z = h1.x + l1.x; r.w = h1.y + l1.y;
    return r;
}
__device__ __forceinline__ void store_hl(__half* __restrict__ h,
                                         __half* __restrict__ l,
                                         int idx, float4 r) {
    __half2 h0 = __floats2half2_rn(r.x, r.y);
    __half2 h1 = __floats2half2_rn(r.z, r.w);
    float2 f0 = __half22float2(h0), f1 = __half22float2(h1);
    __half2 l0 = __floats2half2_rn(r.x - f0.x, r.y - f0.y);
    __half2 l1 = __floats2half2_rn(r.z - f1.x, r.w - f1.y);
    uint2 hu, lu;
    hu.x = *reinterpret_cast<uint32_t*>(&h0);
    hu.y = *reinterpret_cast<uint32_t*>(&h1);
    lu.x = *reinterpret_cast<uint32_t*>(&l0);
    lu.y = *reinterpret_cast<uint32_t*>(&l1);
    ((uint2*)h)[idx] = hu;
    ((uint2*)l)[idx] = lu;
}

// ---------------- gather core (8-wide unroll) ----------------
__device__ __forceinline__ void gacc(float& ax, float& ay, float& az, float& aw,
                                     uint2 u, float w) {
    float2 a = __half22float2(*reinterpret_cast<__half2*>(&u.x));
    float2 b = __half22float2(*reinterpret_cast<__half2*>(&u.y));
    ax += w * a.x; ay += w * a.y; az += w * b.x; aw += w * b.y;
}

__device__ __forceinline__ void gather_row(
    const __half* __restrict__ vinH, int beg, int end, int lane,
    float& ax, float& ay, float& az, float& aw)
{
    int j = beg;
    for (; j + 7 < end; j += 8) {
        int   s[8];
        float w[8];
        uint2 u[8];
        #pragma unroll
        for (int q = 0; q < 8; ++q) { s[q] = g_col[j + q]; w[q] = g_wt[j + q]; }
        #pragma unroll
        for (int q = 0; q < 8; ++q)
            u[q] = ((const uint2*)(vinH + (size_t)s[q] * 128))[lane];
        #pragma unroll
        for (int q = 0; q < 8; ++q) gacc(ax, ay, az, aw, u[q], w[q]);
    }
    for (; j + 1 < end; j += 2) {
        int   s0 = g_col[j],  s1 = g_col[j + 1];
        float w0 = g_wt[j],   w1 = g_wt[j + 1];
        uint2 u0 = ((const uint2*)(vinH + (size_t)s0 * 128))[lane];
        uint2 u1 = ((const uint2*)(vinH + (size_t)s1 * 128))[lane];
        gacc(ax, ay, az, aw, u0, w0);
        gacc(ax, ay, az, aw, u1, w1);
    }
    if (j < end) {
        int   s0 = g_col[j];
        float w0 = g_wt[j];
        uint2 u0 = ((const uint2*)(vinH + (size_t)s0 * 128))[lane];
        gacc(ax, ay, az, aw, u0, w0);
    }
}

// ---------------- SpMV: fp16 gather, fp32 accumulate, hi/lo out ----------
__global__ void k_spmv(const __half* __restrict__ vinH,
                       const __half* __restrict__ prevH,
                       const __half* __restrict__ prevL,
                       __half* __restrict__ voutH,
                       __half* __restrict__ voutL,
                       int cheb) {
    int w    = (blockIdx.x * blockDim.x + threadIdx.x) >> 5;
    int lane = threadIdx.x & 31;
    if (w >= N_NODES) return;

    float4 p = make_float4(0.f, 0.f, 0.f, 0.f);
    if (cheb) p = load_hl(prevH, prevL, w * 32 + lane);

    float ax = 0.f, ay = 0.f, az = 0.f, aw = 0.f;
    gather_row(vinH, g_rp[w], g_rp[w + 1], lane, ax, ay, az, aw);

    float4 r;
    if (cheb) {
        r.x = 2.0f * ax - p.x;
        r.y = 2.0f * ay - p.y;
        r.z = 2.0f * az - p.z;
        r.w = 2.0f * aw - p.w;
    } else {
        r.x = ax; r.y = ay; r.z = az; r.w = aw;
    }
    store_hl(voutH, voutL, w * 32 + lane, r);
}

// ---------------- final SpMV fused with head ----------------
__global__ void k_spmv_out(const __half* __restrict__ T3h, const __half* __restrict__ T3l,
                           const __half* __restrict__ T2h, const __half* __restrict__ T2l,
                           const __half* __restrict__ H2h, const __half* __restrict__ H2l,
                           const __half* __restrict__ T1h, const __half* __restrict__ T1l,
                           float* __restrict__ out) {
    __shared__ float c2[5 * 128];
    for (int i = threadIdx.x; i < 5 * 128; i += blockDim.x) c2[i] = g_C2[i];
    __syncthreads();
    int w    = (blockIdx.x * blockDim.x + threadIdx.x) >> 5;
    int lane = threadIdx.x & 31;
    if (w >= N_NODES) return;

    const int idx = w * 32 + lane;
    float4 p = load_hl(T2h, T2l, idx);

    float ax = 0.f, ay = 0.f, az = 0.f, aw = 0.f;
    gather_row(T3h, g_rp[w], g_rp[w + 1], lane, ax, ay, az, aw);

    float4 t4;
    t4.x = 2.0f * ax - p.x;
    t4.y = 2.0f * ay - p.y;
    t4.z = 2.0f * az - p.z;
    t4.w = 2.0f * aw - p.w;

    const int c = lane * 4;
    float s;
    {
        const float* w4 = c2 + 4 * 128 + c;
        s = t4.x * w4[0] + t4.y * w4[1] + t4.z * w4[2] + t4.w * w4[3];
    }
    {
        float4 h = load_hl(H2h, H2l, idx);
        const float* w0 = c2 + 0 * 128 + c;
        s += h.x * w0[0] + h.y * w0[1] + h.z * w0[2] + h.w * w0[3];
    }
    {
        float4 h = load_hl(T1h, T1l, idx);
        const float* w1 = c2 + 1 * 128 + c;
        s += h.x * w1[0] + h.y * w1[1] + h.z * w1[2] + h.w * w1[3];
    }
    {
        const float* w2 = c2 + 2 * 128 + c;
        s += p.x * w2[0] + p.y * w2[1] + p.z * w2[2] + p.w * w2[3];
    }
    {
        float4 h = load_hl(T3h, T3l, idx);
        const float* w3 = c2 + 3 * 128 + c;
        s += h.x * w3[0] + h.y * w3[1] + h.z * w3[2] + h.w * w3[3];
    }
    #pragma unroll
    for (int off = 16; off > 0; off >>= 1) s += __shfl_xor_sync(0xFFFFFFFFu, s, off);
    if (lane == 0) out[w] = s + g_c0[0];
}

// ---------------- tensor-core GEMM: cp.async double-buffered ----------
struct P5 { const __half* h[5]; const __half* l[5]; };

__device__ __forceinline__ void mma16816(float* d, const uint32_t* a, const uint32_t* b) {
    asm volatile(
        "mma.sync.aligned.m16n8k16.row.col.f32.f16.f16.f32 "
        "{%0,%1,%2,%3}, {%4,%5,%6,%7}, {%8,%9}, {%0,%1,%2,%3};"
        : "+f"(d[0]), "+f"(d[1]), "+f"(d[2]), "+f"(d[3])
        : "r"(a[0]), "r"(a[1]), "r"(a[2]), "r"(a[3]), "r"(b[0]), "r"(b[1]));
}

__device__ __forceinline__ void cpa16(uint32_t dst, const void* src, int srcsize) {
    asm volatile("cp.async.cg.shared.global [%0], [%1], 16, %2;"
                 :: "r"(dst), "l"(src), "r"(srcsize));
}

template <bool RELU>
__global__ __launch_bounds__(256, 2)
void k_gemm_mma(P5 A, const __half* __restrict__ Bh, const __half* __restrict__ Bl,
                const float* __restrict__ bias,
                __half* __restrict__ Ch, __half* __restrict__ Cl) {
    extern __shared__ __align__(16) __half sm[];
    const int ARR = 128 * AP;

    const int tid  = threadIdx.x;
    const int wid  = tid >> 5, lane = tid & 31;
    const int g    = lane >> 2, t = lane & 3;
    const int wm   = wid & 3;
    const int wn   = wid >> 2;
    const int m0   = blockIdx.x * 128;

    uint32_t smBase;
    asm("{ .reg .u64 tt; cvta.to.shared.u64 tt, %1; cvt.u32.u64 %0, tt; }"
        : "=r"(smBase) : "l"(sm));

    float acc[2][8][4];
    #pragma unroll
    for (int mt = 0; mt < 2; ++mt)
        #pragma unroll
        for (int nt = 0; nt < 8; ++nt)
            #pragma unroll
            for (int q = 0; q < 4; ++q) acc[mt][nt][q] = 0.f;

    auto do_stage = [&](int c, int buf) {
        const int s = c >> 2, k0 = (c & 3) * 32;
        const __half* Ah = A.h[s];
        const __half* Al = A.l[s];
        const size_t bofs = (size_t)s * 16384 + k0;
        const uint32_t base = smBase + (uint32_t)(buf * 4 * ARR) * 2;
        #pragma unroll
        for (int i = 0; i < 2; ++i) {
            int q = tid + i * 256;
            int row = q >> 2, seg = q & 3;
            int gm = m0 + row;
            int ok  = (gm < N_NODES) ? 16 : 0;
            int gmc = (gm < N_NODES) ? gm : 0;
            uint32_t so = (uint32_t)((row * AP + seg * 8) * 2);
            cpa16(base + 0 * ARR * 2 + so, Ah + (size_t)gmc * 128 + k0 + seg * 8, ok);
            cpa16(base + 1 * ARR * 2 + so, Al + (size_t)gmc * 128 + k0 + seg * 8, ok);
            cpa16(base + 2 * ARR * 2 + so, Bh + bofs + (size_t)row * 128 + seg * 8, 16);
            cpa16(base + 3 * ARR * 2 + so, Bl + bofs + (size_t)row * 128 + seg * 8, 16);
        }
    };

    do_stage(0, 0);
    asm volatile("cp.async.commit_group;" ::: "memory");

    #pragma unroll 1
    for (int c = 0; c < 20; ++c) {
        const int cur = c & 1;
        if (c + 1 < 20) {
            do_stage(c + 1, cur ^ 1);
            asm volatile("cp.async.commit_group;" ::: "memory");
            asm volatile("cp.async.wait_group 1;" ::: "memory");
        } else {
            asm volatile("cp.async.wait_group 0;" ::: "memory");
        }
        __syncthreads();

        const __half* pAh = sm + (cur * 4 + 0) * ARR;
        const __half* pAl = sm + (cur * 4 + 1) * ARR;
        const __half* pBh = sm + (cur * 4 + 2) * ARR;
        const __half* pBl = sm + (cur * 4 + 3) * ARR;

        #pragma unroll
        for (int ks = 0; ks < 2; ++ks) {
            const int kb = ks * 16 + 2 * t;
            uint32_t bf[8][2], ah[2][4], al[2][4];
            #pragma unroll
            for (int nt = 0; nt < 8; ++nt) {
                const int nb = (wn * 64 + nt * 8 + g) * AP + kb;
                bf[nt][0] = *(const uint32_t*)&pBh[nb];
                bf[nt][1] = *(const uint32_t*)&pBh[nb + 8];
            }
            #pragma unroll
            for (int mt = 0; mt < 2; ++mt) {
                const int rb = (wm * 32 + mt * 16 + g) * AP + kb;
                ah[mt][0] = *(const uint32_t*)&pAh[rb];
                ah[mt][1] = *(const uint32_t*)&pAh[rb + 8 * AP];
                ah[mt][2] = *(const uint32_t*)&pAh[rb + 8];
                ah[mt][3] = *(const uint32_t*)&pAh[rb + 8 * AP + 8];
                al[mt][0] = *(const uint32_t*)&pAl[rb];
                al[mt][1] = *(const uint32_t*)&pAl[rb + 8 * AP];
                al[mt][2] = *(const uint32_t*)&pAl[rb + 8];
                al[mt][3] = *(const uint32_t*)&pAl[rb + 8 * AP + 8];
            }
            #pragma unroll
            for (int mt = 0; mt < 2; ++mt)
                #pragma unroll
                for (int nt = 0; nt < 8; ++nt) mma16816(acc[mt][nt], ah[mt], bf[nt]);
            #pragma unroll
            for (int mt = 0; mt < 2; ++mt)
                #pragma unroll
                for (int nt = 0; nt < 8; ++nt) mma16816(acc[mt][nt], al[mt], bf[nt]);
            #pragma unroll
            for (int nt = 0; nt < 8; ++nt) {
                const int nb = (wn * 64 + nt * 8 + g) * AP + kb;
                bf[nt][0] = *(const uint32_t*)&pBl[nb];
                bf[nt][1] = *(const uint32_t*)&pBl[nb + 8];
            }
            #pragma unroll
            for (int mt = 0; mt < 2; ++mt)
                #pragma unroll
                for (int nt = 0; nt < 8; ++nt) mma16816(acc[mt][nt], ah[mt], bf[nt]);
        }
        __syncthreads();
    }

    // ---- epilogue: bias (+relu), hi + lo shadow ----
    #pragma unroll
    for (int mt = 0; mt < 2; ++mt) {
        #pragma unroll
        for (int half = 0; half < 2; ++half) {
            const int row = m0 + wm * 32 + mt * 16 + g + half * 8;
            if (row < N_NODES) {
                #pragma unroll
                for (int nt = 0; nt < 8; ++nt) {
                    const int col = wn * 64 + nt * 8 + 2 * t;
                    float v0 = acc[mt][nt][half * 2 + 0] + __ldg(bias + col);
                    float v1 = acc[mt][nt][half * 2 + 1] + __ldg(bias + col + 1);
                    if (RELU) { v0 = fmaxf(v0, 0.f); v1 = fmaxf(v1, 0.f); }
                    __half2 h2 = __floats2half2_rn(v0, v1);
                    float2 hf = __half22float2(h2);
                    __half2 l2 = __floats2half2_rn(v0 - hf.x, v1 - hf.y);
                    *(uint32_t*)(Ch + (size_t)row * 128 + col) =
                        *reinterpret_cast<uint32_t*>(&h2);
                    *(uint32_t*)(Cl + (size_t)row * 128 + col) =
                        *reinterpret_cast<uint32_t*>(&l2);
                }
            }
        }
    }
}

// ---------------- launch --------------------------------------------------
extern "C" void kernel_launch(void* const* d_in, const int* in_sizes, int n_in,
                              void* d_out, int out_size) {
    const float* x  = (const float*)d_in[0];
    const int*   ei = (const int*)  d_in[1];
    const float* W0 = (const float*)d_in[2];
    const float* b0 = (const float*)d_in[3];
    const float* W1 = (const float*)d_in[4];
    const float* b1 = (const float*)d_in[5];
    const float* W2 = (const float*)d_in[6];
    const float* b2 = (const float*)d_in[7];
    const float* Wl = (const float*)d_in[8];
    const float* bl = (const float*)d_in[9];
    float* out = (float*)d_out;

    __half *Xh, *Xl, *T1h, *T1l, *T2h, *T2l, *T3h, *T3l, *T4h, *T4l;
    __half *Hh, *Hl, *H2h, *H2l;
    __half *W0th, *W0tl, *W1th, *W1tl;
    cudaGetSymbolAddress((void**)&Xh,   g_Xh);
    cudaGetSymbolAddress((void**)&Xl,   g_Xl);
    cudaGetSymbolAddress((void**)&T1h,  g_T1h);
    cudaGetSymbolAddress((void**)&T1l,  g_T1l);
    cudaGetSymbolAddress((void**)&T2h,  g_T2h);
    cudaGetSymbolAddress((void**)&T2l,  g_T2l);
    cudaGetSymbolAddress((void**)&T3h,  g_T3h);
    cudaGetSymbolAddress((void**)&T3l,  g_T3l);
    cudaGetSymbolAddress((void**)&T4h,  g_T4h);
    cudaGetSymbolAddress((void**)&T4l,  g_T4l);
    cudaGetSymbolAddress((void**)&Hh,   g_Hh);
    cudaGetSymbolAddress((void**)&Hl,   g_Hl);
    cudaGetSymbolAddress((void**)&H2h,  g_H2h);
    cudaGetSymbolAddress((void**)&H2l,  g_H2l);
    cudaGetSymbolAddress((void**)&W0th, g_W0th);
    cudaGetSymbolAddress((void**)&W0tl, g_W0tl);
    cudaGetSymbolAddress((void**)&W1th, g_W1th);
    cudaGetSymbolAddress((void**)&W1tl, g_W1tl);

    cudaFuncSetAttribute(k_gemm_mma<true>,
                         cudaFuncAttributeMaxDynamicSharedMemorySize, SMEM_BYTES);

    const int nb_n = (N_NODES + 255) / 256;
    const int spmv_blocks = (N_NODES * 32 + 255) / 256;
    const int gemm_blocks = (N_NODES + 127) / 128;

    k_zero      <<<nb_n, 256>>>();
    k_count_init<<<CI_BLOCKS, 256>>>(ei, W0, W1, W2, b2, Wl, bl, x,
                                     W0th, W0tl, W1th, W1tl, Xh, Xl);
    k_scanA     <<<SCAN_B, 1024>>>();
    k_scanC     <<<SCAN_B, 1024>>>();
    k_fill      <<<NB_E, 256>>>(ei);

    // ---- layer 0 (T0 = x) ----
    k_spmv<<<spmv_blocks, 256>>>(Xh,  nullptr, nullptr, T1h, T1l, 0);
    k_spmv<<<spmv_blocks, 256>>>(T1h, Xh,  Xl,  T2h, T2l, 1);
    k_spmv<<<spmv_blocks, 256>>>(T2h, T1h, T1l, T3h, T3l, 1);
    k_spmv<<<spmv_blocks, 256>>>(T3h, T2h, T2l, T4h, T4l, 1);
    { P5 a;
      a.h[0]=Xh;  a.h[1]=T1h; a.h[2]=T2h; a.h[3]=T3h; a.h[4]=T4h;
      a.l[0]=Xl;  a.l[1]=T1l; a.l[2]=T2l; a.l[3]=T3l; a.l[4]=T4l;
      k_gemm_mma<true><<<gemm_blocks, 256, SMEM_BYTES>>>(
          a, W0th, W0tl, b0, Hh, Hl); }

    // ---- layer 1 (T0 = H) ----
    k_spmv<<<spmv_blocks, 256>>>(Hh,  nullptr, nullptr, T1h, T1l, 0);
    k_spmv<<<spmv_blocks, 256>>>(T1h, Hh,  Hl,  T2h, T2l, 1);
    k_spmv<<<spmv_blocks, 256>>>(T2h, T1h, T1l, T3h, T3l, 1);
    k_spmv<<<spmv_blocks, 256>>>(T3h, T2h, T2l, T4h, T4l, 1);
    { P5 a;
      a.h[0]=Hh;  a.h[1]=T1h; a.h[2]=T2h; a.h[3]=T3h; a.h[4]=T4h;
      a.l[0]=Hl;  a.l[1]=T1l; a.l[2]=T2l; a.l[3]=T3l; a.l[4]=T4l;
      k_gemm_mma<true><<<gemm_blocks, 256, SMEM_BYTES>>>(
          a, W1th, W1tl, b1, H2h, H2l); }

    // ---- layer 2 (T0 = H2): 3 SpMVs, then final SpMV fused with head ----
    k_spmv<<<spmv_blocks, 256>>>(H2h, nullptr, nullptr, T1h, T1l, 0);
    k_spmv<<<spmv_blocks, 256>>>(T1h, H2h, H2l, T2h, T2l, 1);
    k_spmv<<<spmv_blocks, 256>>>(T2h, T1h, T1l, T3h, T3l, 1);
    k_spmv_out<<<spmv_blocks, 256>>>(T3h, T3l, T2h, T2l, H2h, H2l, T1h, T1l, out);
}